// round 17
// baseline (speedup 1.0000x reference)
#include <cuda_runtime.h>
#include <cuda_fp16.h>

#define N_NODES 50000
#define N_EDGES 400000
#define NODE_IN 16
#define EDGE_IN 8
#define HID 16
#define TROWP_H 320  // halves per node in gmem: 17x16 + pad -> 640B = 5 lines
#define NPB 40       // nodes per block in node kernels (50000 = 1250*40 exact)
#define NTH 160      // threads: 16 o-lanes x 10 groups of 4 nodes
#define NODE_GRID 1250
#define SROW 324     // halves per node row in smem tile (648B; bank-spread pad)

// PDL: successor may launch early; wait orders against predecessor completion.
#define PDL_TRIGGER() asm volatile("griddepcontrol.launch_dependents;" ::: "memory")
#define PDL_WAIT()    asm volatile("griddepcontrol.wait;" ::: "memory")

// dynamic smem partition (node kernels)
#define W2D_BYTES   (17 * 256 * 8)                 // dup'd w2+b2 rows: 34816
#define TST_BYTES   (NPB * SROW * 2)               // 25920
#define PRE_DSM     (W2D_BYTES + TST_BYTES)        // 60736
#define UPD_DSM     (W2D_BYTES + TST_BYTES + 2048) // + dup'd roots: 62784

// Scratch (device globals: no allocation allowed)
__device__ __half g_Th[N_NODES * TROWP_H];  // factored tensor, fp16 (32 MB)
__device__ float g_sum1[N_NODES * HID];
__device__ float g_sum2[N_NODES * HID];
__device__ float g_cnt[N_NODES];
__device__ float g_h1[N_NODES * HID];

// f32x2 packed helpers (Blackwell packed fp32 pipe)
__device__ __forceinline__ unsigned long long pack2(float x, float y) {
    unsigned long long r;
    asm("mov.b64 %0, {%1, %2};" : "=l"(r) : "f"(x), "f"(y));
    return r;
}
__device__ __forceinline__ void unpack2(unsigned long long v, float& x, float& y) {
    asm("mov.b64 {%0, %1}, %2;" : "=f"(x), "=f"(y) : "l"(v));
}
#define FFMA2(acc, a, b) \
    asm("fma.rn.f32x2 %0, %1, %2, %0;" : "+l"(acc) : "l"(a), "l"(b))

// Coalesced writeout of the staged T tile: NPB*640B as uint2, 20 per thread.
__device__ __forceinline__ void tile_writeout(const __half* Tst, int nb, int tid) {
    const char* sbase = (const char*)Tst;
    char* gbase = (char*)(g_Th + (long long)nb * TROWP_H);
    #pragma unroll
    for (int j = 0; j < 20; j++) {
        int idx = tid + j * NTH;         // 0..3199 uint2 slots
        int node = idx / 80;
        int c8 = idx % 80;               // 8B chunk within node row
        *(uint2*)(gbase + node * 640 + c8 * 8) =
            *(const uint2*)(sbase + node * 648 + c8 * 8);
    }
}

// ---------------------------------------------------------------------------
// Layer-1 per-node precompute: T[n][k][o] = sum_i x[n,i] * w2[k, i*16+o]
//                              row 16     = sum_i x[n,i] * b2[i*16+o]
// Thread = (o, 4 nodes as 2 packed pairs); weights dup'd (w,w) in smem so one
// LDS.64 feeds 4 nodes via 2 x fma.rn.f32x2. T staged in smem, uint2 writeout.
// Fused: accumulator zeroing.
__global__ void __launch_bounds__(NTH, 2) k_precompute(const float* __restrict__ x,
                                                       const float* __restrict__ w2,
                                                       const float* __restrict__ b2) {
    extern __shared__ char dsm[];
    float2* w2d = (float2*)dsm;                       // 17*256 dup'd entries
    __half* Tst = (__half*)(dsm + W2D_BYTES);         // NPB * SROW halves
    __shared__ __align__(16) float xs[NPB * NODE_IN];
    int tid = threadIdx.x;
    int gid = blockIdx.x * NTH + tid;
    PDL_TRIGGER();

    // fused zeroing of accumulators (kernel boundary orders vs. edge pass)
    const int TOT = NODE_GRID * NTH;    // 200000
    for (int j = gid; j < N_NODES * HID; j += TOT) { g_sum1[j] = 0.f; g_sum2[j] = 0.f; }
    if (gid < N_NODES) g_cnt[gid] = 0.f;

    // load dup'd weights: rows 0-15 w2, row 16 b2
    for (int i = tid; i < 16 * 256; i += NTH) {
        float w = w2[i];
        w2d[i] = make_float2(w, w);
    }
    for (int i = tid; i < 256; i += NTH) {
        float w = b2[i];
        w2d[16 * 256 + i] = make_float2(w, w);
    }
    int nb = blockIdx.x * NPB;
    for (int idx = tid; idx < NPB * NODE_IN; idx += NTH)
        xs[idx] = x[(long long)nb * NODE_IN + idx];
    __syncthreads();

    int o = tid & 15;            // output lane
    int g = tid >> 4;            // node group 0..9 (4 nodes each)
    int nl = 4 * g;

    // node-pair packs of x: xp[pr][i] = (x[nl+2pr][i], x[nl+2pr+1][i])
    unsigned long long xp[2][NODE_IN];
    #pragma unroll
    for (int pr = 0; pr < 2; pr++)
        #pragma unroll
        for (int i = 0; i < NODE_IN; i++)
            xp[pr][i] = pack2(xs[(nl + 2 * pr) * NODE_IN + i],
                              xs[(nl + 2 * pr + 1) * NODE_IN + i]);

    #pragma unroll 1
    for (int k = 0; k < 17; k++) {
        unsigned long long a0 = 0ull, a1 = 0ull;
        #pragma unroll
        for (int i = 0; i < NODE_IN; i++) {
            unsigned long long wp =
                *(const unsigned long long*)&w2d[k * 256 + i * 16 + o];  // LDS.64 dup
            FFMA2(a0, xp[0][i], wp);
            FFMA2(a1, xp[1][i], wp);
        }
        float f0, f1, f2, f3;
        unpack2(a0, f0, f1);
        unpack2(a1, f2, f3);
        Tst[(nl + 0) * SROW + k * 16 + o] = __float2half_rn(f0);
        Tst[(nl + 1) * SROW + k * 16 + o] = __float2half_rn(f1);
        Tst[(nl + 2) * SROW + k * 16 + o] = __float2half_rn(f2);
        Tst[(nl + 3) * SROW + k * 16 + o] = __float2half_rn(f3);
    }
    __syncthreads();
    tile_writeout(Tst, nb, tid);
}

// ---------------------------------------------------------------------------
// Edge pass, 8 lanes/edge, fp16 T, 5 x LDG.128 gather (640B/edge).
// Lane l in [0,8): uint4 load r holds halves k = 4r + (l>>1), o = (l&1)*8 + j.
// Bias row (k=16) lives in r=4 for l<2. Contraction in packed fp16 (HFMA2).
// Fold: split-exchange xor-4 then xor-2 reduce in fp32 -> 8 SHFL.
// Writers {0,1,4,5} each RED one o-quad. 256 threads = 32 edges/block.
// PDL: prologue (w1 smem, idx/ea loads, edge MLP) runs pre-wait; T gather
// and REDs run post-wait. Index width detected per-CTA from raw input.
__global__ void __launch_bounds__(256) k_edge(const float* __restrict__ ea,
                                              const void* __restrict__ eidx,
                                              const float* __restrict__ w1,
                                              const float* __restrict__ b1,
                                              int layer) {
    __shared__ float w1s[EDGE_IN * HID];
    __shared__ float b1s[HID];
    __shared__ int s_is64;
    int tid = threadIdx.x;
    PDL_TRIGGER();
    if (tid < EDGE_IN * HID) w1s[tid] = w1[tid];
    if (tid < HID) b1s[tid] = b1[tid];
    if (tid == 0) {
        // int64 vs int32 detection from the input itself
        const int* ei_raw = (const int*)eidx;
        int odd = 0;
        #pragma unroll
        for (int k = 0; k < 8; k++) odd |= ei_raw[2 * k + 1];
        s_is64 = (odd == 0) ? 1 : 0;
    }
    __syncthreads();

    int lane = tid & 31;
    int l = lane & 7;
    int a = l >> 1;
    int base = lane & ~7;                // 8-lane group base within warp
    int e = blockIdx.x * 32 + (tid >> 5) * 4 + (lane >> 3);

    int src, dst;
    if (s_is64) {
        const long long* ei = (const long long*)eidx;
        src = (int)ei[e];
        dst = (int)ei[N_EDGES + e];
    } else {
        const int* ei = (const int*)eidx;
        src = ei[e];
        dst = ei[N_EDGES + e];
    }

    // edge MLP: every lane loads all 8 ea values (broadcast within group)
    const float4* eap = (const float4*)(ea + (long long)e * EDGE_IN);
    float4 a0 = eap[0], a1 = eap[1];
    float eav[EDGE_IN] = {a0.x, a0.y, a0.z, a0.w, a1.x, a1.y, a1.z, a1.w};
    float hA = b1s[l], hB = b1s[l + 8];
    #pragma unroll
    for (int i = 0; i < EDGE_IN; i++) {
        hA += eav[i] * w1s[i * HID + l];
        hB += eav[i] * w1s[i * HID + l + 8];
    }
    hA = fmaxf(hA, 0.f);
    hB = fmaxf(hB, 0.f);

    // pack (hA,hB) -> half2; one shuffle moves both h values
    __half2 hpk = __floats2half2_rn(hA, hB);
    unsigned int hbits = *(unsigned int*)&hpk;
    unsigned int u0 = __shfl_sync(0xffffffffu, hbits, base + a);      // (h[a], h[8+a])
    unsigned int u1 = __shfl_sync(0xffffffffu, hbits, base + 4 + a);  // (h[4+a], h[12+a])
    __half2 h2_0 = *(__half2*)&u0;
    __half2 h2_1 = *(__half2*)&u1;
    __half2 hd[4];
    hd[0] = __low2half2(h2_0);   // h[a]
    hd[1] = __low2half2(h2_1);   // h[4+a]
    hd[2] = __high2half2(h2_0);  // h[8+a]
    hd[3] = __high2half2(h2_1);  // h[12+a]

    // ---- wait for predecessor (T producer / accumulator zeroing) ----
    PDL_WAIT();

    // gather fp16 T: 5 x LDG.128, one 128B line per (r, edge)
    const uint4* tp = (const uint4*)(g_Th + (long long)src * TROWP_H);
    uint4 t[5];
    #pragma unroll
    for (int r = 0; r < 5; r++) t[r] = tp[r * 8 + l];

    // fp16 packed contraction: 4-term HFMA2 chains per o-pair
    __half2 acc2[4];
    if (l < 2) {                         // bias row (k=16) in t[4]
        const __half2* bp = (const __half2*)&t[4];
        #pragma unroll
        for (int q = 0; q < 4; q++) acc2[q] = bp[q];
    } else {
        __half2 z = __floats2half2_rn(0.f, 0.f);
        #pragma unroll
        for (int q = 0; q < 4; q++) acc2[q] = z;
    }
    #pragma unroll
    for (int r = 0; r < 4; r++) {
        const __half2* hp = (const __half2*)&t[r];
        #pragma unroll
        for (int q = 0; q < 4; q++)
            acc2[q] = __hfma2(hd[r], hp[q], acc2[q]);
    }

    // convert 4 half2 accs -> 8 fp32
    float acc[8];
    #pragma unroll
    for (int q = 0; q < 4; q++) {
        float2 f = __half22float2(acc2[q]);
        acc[2 * q] = f.x;
        acc[2 * q + 1] = f.y;
    }

    // fold over a (4 lanes per parity): split-exchange then reduce -> 8 SHFL
    int s = (l >> 2) & 1;                // which quad this lane keeps
    float res[4];
    #pragma unroll
    for (int j = 0; j < 4; j++) {
        float send = s ? acc[j] : acc[j + 4];
        float got = __shfl_xor_sync(0xffffffffu, send, 4);
        res[j] = (s ? acc[j + 4] : acc[j]) + got;
    }
    #pragma unroll
    for (int j = 0; j < 4; j++)
        res[j] += __shfl_xor_sync(0xffffffffu, res[j], 2);

    if ((l & 2) == 0) {                  // writers: l in {0,1,4,5}
        int o0 = (l & 1) * 8 + (l >> 2) * 4;
        float* sum_out = (layer == 1) ? g_sum1 : g_sum2;
        float* p = sum_out + (long long)dst * HID + o0;
        asm volatile("red.global.add.v4.f32 [%0], {%1, %2, %3, %4};"
                     :: "l"(p), "f"(res[0]), "f"(res[1]),
                        "f"(res[2]), "f"(res[3])
                     : "memory");
    }
    if (layer == 1 && l == 0) atomicAdd(&g_cnt[dst], 1.f);
}

// ---------------------------------------------------------------------------
// Layer-1 update (scatter-mean + root + bias + relu) fused with layer-2
// precompute of T (fp16) from h1. Same 4-node dup'd-weight structure.
// PDL: weight smem loads + x staging pre-wait; g_cnt/g_sum1 reads post-wait.
__global__ void __launch_bounds__(NTH, 2) k_update1_pre2(const float* __restrict__ x,
                                                         const float* __restrict__ root1,
                                                         const float* __restrict__ bias1,
                                                         const float* __restrict__ w2,
                                                         const float* __restrict__ b2) {
    extern __shared__ char dsm[];
    float2* w2d = (float2*)dsm;                       // 17*256 dup'd entries
    __half* Tst = (__half*)(dsm + W2D_BYTES);
    float2* rootd = (float2*)(dsm + W2D_BYTES + TST_BYTES);  // 256 dup'd entries
    __shared__ __align__(16) float xs[NPB * NODE_IN];
    __shared__ __align__(16) float hs[NPB * HID];
    __shared__ float biass[HID];
    int tid = threadIdx.x;
    PDL_TRIGGER();
    for (int i = tid; i < 16 * 256; i += NTH) {
        float w = w2[i];
        w2d[i] = make_float2(w, w);
    }
    for (int i = tid; i < 256; i += NTH) {
        float w = b2[i];
        w2d[16 * 256 + i] = make_float2(w, w);
        float r = root1[i];
        rootd[i] = make_float2(r, r);
    }
    if (tid < HID) biass[tid] = bias1[tid];

    int nb = blockIdx.x * NPB;
    for (int idx = tid; idx < NPB * NODE_IN; idx += NTH)
        xs[idx] = x[(long long)nb * NODE_IN + idx];
    __syncthreads();

    int o = tid & 15;
    int g = tid >> 4;
    int nl = 4 * g;

    // node-pair packs of x (pre-wait; input only)
    unsigned long long xp[2][NODE_IN];
    #pragma unroll
    for (int pr = 0; pr < 2; pr++)
        #pragma unroll
        for (int i = 0; i < NODE_IN; i++)
            xp[pr][i] = pack2(xs[(nl + 2 * pr) * NODE_IN + i],
                              xs[(nl + 2 * pr + 1) * NODE_IN + i]);

    // ---- wait for edge pass 1 (g_sum1 / g_cnt producers) ----
    PDL_WAIT();

    // stage 1: layer-1 node update for 4 nodes at output o
    float hval[4];
    #pragma unroll
    for (int pr = 0; pr < 2; pr++) {
        int na = nb + nl + 2 * pr;
        float ia = 1.f / fmaxf(g_cnt[na], 1.f);
        float ib = 1.f / fmaxf(g_cnt[na + 1], 1.f);
        float sa = g_sum1[(long long)na * HID + o] * ia + biass[o];
        float sb = g_sum1[(long long)(na + 1) * HID + o] * ib + biass[o];
        unsigned long long acc = pack2(sa, sb);
        #pragma unroll
        for (int i = 0; i < NODE_IN; i++) {
            unsigned long long rp = *(const unsigned long long*)&rootd[i * 16 + o];
            FFMA2(acc, xp[pr][i], rp);
        }
        unpack2(acc, sa, sb);
        hval[2 * pr] = fmaxf(sa, 0.f);
        hval[2 * pr + 1] = fmaxf(sb, 0.f);
    }
    #pragma unroll
    for (int j = 0; j < 4; j++) {
        g_h1[(long long)(nb + nl + j) * HID + o] = hval[j];
        hs[(nl + j) * HID + o] = hval[j];
    }
    __syncthreads();

    // stage 2: layer-2 T precompute from h1 (node-pair packs of h)
    unsigned long long hp[2][HID];
    #pragma unroll
    for (int pr = 0; pr < 2; pr++)
        #pragma unroll
        for (int i = 0; i < HID; i++)
            hp[pr][i] = pack2(hs[(nl + 2 * pr) * HID + i],
                              hs[(nl + 2 * pr + 1) * HID + i]);

    #pragma unroll 1
    for (int k = 0; k < 17; k++) {
        unsigned long long a0 = 0ull, a1 = 0ull;
        #pragma unroll
        for (int i = 0; i < HID; i++) {
            unsigned long long wp =
                *(const unsigned long long*)&w2d[k * 256 + i * 16 + o];
            FFMA2(a0, hp[0][i], wp);
            FFMA2(a1, hp[1][i], wp);
        }
        float f0, f1, f2, f3;
        unpack2(a0, f0, f1);
        unpack2(a1, f2, f3);
        Tst[(nl + 0) * SROW + k * 16 + o] = __float2half_rn(f0);
        Tst[(nl + 1) * SROW + k * 16 + o] = __float2half_rn(f1);
        Tst[(nl + 2) * SROW + k * 16 + o] = __float2half_rn(f2);
        Tst[(nl + 3) * SROW + k * 16 + o] = __float2half_rn(f3);
    }
    __syncthreads();
    tile_writeout(Tst, nb, tid);
}

// ---------------------------------------------------------------------------
// Layer-2 update + q head. One thread per node. PDL: weight smem pre-wait.
__global__ void __launch_bounds__(256) k_final(const float* __restrict__ root2,
                                               const float* __restrict__ bias2,
                                               const float* __restrict__ qw,
                                               const float* __restrict__ qb,
                                               float* __restrict__ out) {
    __shared__ float roots[HID * HID];
    __shared__ float biass[HID];
    __shared__ float qws[HID];
    int tid = threadIdx.x;
    PDL_TRIGGER();
    roots[tid] = root2[tid];
    if (tid < HID) { biass[tid] = bias2[tid]; qws[tid] = qw[tid]; }
    __syncthreads();

    // ---- wait for edge pass 2 (g_sum2 producer) ----
    PDL_WAIT();

    int n = blockIdx.x * 256 + tid;
    if (n >= N_NODES) return;
    float inv = 1.f / fmaxf(g_cnt[n], 1.f);
    float h1v[HID];
    const float4* h1p = (const float4*)&g_h1[(long long)n * HID];
    #pragma unroll
    for (int i = 0; i < HID / 4; i++) {
        float4 v = h1p[i];
        h1v[i * 4 + 0] = v.x; h1v[i * 4 + 1] = v.y;
        h1v[i * 4 + 2] = v.z; h1v[i * 4 + 3] = v.w;
    }
    float res = qb[0];
    #pragma unroll
    for (int o = 0; o < HID; o++) {
        float h2 = g_sum2[(long long)n * HID + o] * inv + biass[o];
        #pragma unroll
        for (int i = 0; i < HID; i++) h2 += h1v[i] * roots[i * HID + o];
        h2 = fmaxf(h2, 0.f);
        res += h2 * qws[o];
    }
    out[n] = res;
}

// ---------------------------------------------------------------------------
extern "C" void kernel_launch(void* const* d_in, const int* in_sizes, int n_in,
                              void* d_out, int out_size) {
    const float* x        = (const float*)d_in[0];
    const float* edge_attr= (const float*)d_in[1];
    const float* e1_w1    = (const float*)d_in[2];
    const float* e1_b1    = (const float*)d_in[3];
    const float* e1_w2    = (const float*)d_in[4];
    const float* e1_b2    = (const float*)d_in[5];
    const float* root1    = (const float*)d_in[6];
    const float* bias1    = (const float*)d_in[7];
    const float* e2_w1    = (const float*)d_in[8];
    const float* e2_b1    = (const float*)d_in[9];
    const float* e2_w2    = (const float*)d_in[10];
    const float* e2_b2    = (const float*)d_in[11];
    const float* root2    = (const float*)d_in[12];
    const float* bias2    = (const float*)d_in[13];
    const float* q_w      = (const float*)d_in[14];
    const float* q_b      = (const float*)d_in[15];
    const void*  eidx     = d_in[16];
    float* out = (float*)d_out;

    // allow >48KB dynamic smem for the node kernels (immediate API; capture-safe)
    cudaFuncSetAttribute(k_precompute,
                         cudaFuncAttributeMaxDynamicSharedMemorySize, PRE_DSM);
    cudaFuncSetAttribute(k_update1_pre2,
                         cudaFuncAttributeMaxDynamicSharedMemorySize, UPD_DSM);

    cudaLaunchAttribute pdl_attr[1];
    pdl_attr[0].id = cudaLaunchAttributeProgrammaticStreamSerialization;
    pdl_attr[0].val.programmaticStreamSerializationAllowed = 1;

    // kernel 1: normal launch (dynamic smem)
    k_precompute<<<NODE_GRID, NTH, PRE_DSM>>>(x, e1_w2, e1_b2);

    {   // kernel 2: edge pass layer 1
        cudaLaunchConfig_t cfg = {};
        cfg.gridDim = dim3(N_EDGES / 32);
        cfg.blockDim = dim3(256);
        cfg.attrs = pdl_attr;
        cfg.numAttrs = 1;
        cudaLaunchKernelEx(&cfg, k_edge, edge_attr, (const void*)eidx,
                           e1_w1, e1_b1, 1);
    }
    {   // kernel 3: update1 + precompute2
        cudaLaunchConfig_t cfg = {};
        cfg.gridDim = dim3(NODE_GRID);
        cfg.blockDim = dim3(NTH);
        cfg.dynamicSmemBytes = UPD_DSM;
        cfg.attrs = pdl_attr;
        cfg.numAttrs = 1;
        cudaLaunchKernelEx(&cfg, k_update1_pre2, x, root1, bias1, e2_w2, e2_b2);
    }
    {   // kernel 4: edge pass layer 2
        cudaLaunchConfig_t cfg = {};
        cfg.gridDim = dim3(N_EDGES / 32);
        cfg.blockDim = dim3(256);
        cfg.attrs = pdl_attr;
        cfg.numAttrs = 1;
        cudaLaunchKernelEx(&cfg, k_edge, edge_attr, (const void*)eidx,
                           e2_w1, e2_b1, 2);
    }
    {   // kernel 5: final update + q head
        cudaLaunchConfig_t cfg = {};
        cfg.gridDim = dim3((N_NODES + 255) / 256);
        cfg.blockDim = dim3(256);
        cfg.attrs = pdl_attr;
        cfg.numAttrs = 1;
        cudaLaunchKernelEx(&cfg, k_final, root2, bias2, q_w, q_b, out);
    }
}